// round 4
// baseline (speedup 1.0000x reference)
#include <cuda_runtime.h>

// ---------------------------------------------------------------------------
// Packed f32x2 helpers (FFMA2 path — ptxas won't auto-generate these)
// ---------------------------------------------------------------------------
#define DEV_INLINE __device__ __forceinline__

DEV_INLINE unsigned long long pack2(float x) {
    unsigned long long r;
    asm("mov.b64 %0, {%1, %1};" : "=l"(r) : "r"(__float_as_uint(x)));
    return r;
}
DEV_INLINE unsigned long long pack2(float x, float y) {
    unsigned long long r;
    asm("mov.b64 %0, {%1, %2};" : "=l"(r) : "r"(__float_as_uint(x)), "r"(__float_as_uint(y)));
    return r;
}
DEV_INLINE void fma2(unsigned long long& d, unsigned long long a, unsigned long long b) {
    asm("fma.rn.f32x2 %0, %1, %2, %0;" : "+l"(d) : "l"(a), "l"(b));
}
DEV_INLINE float2 unpack2(unsigned long long v) {
    unsigned int lo, hi;
    asm("mov.b64 {%0, %1}, %2;" : "=r"(lo), "=r"(hi) : "l"(v));
    return make_float2(__uint_as_float(lo), __uint_as_float(hi));
}

// ---------------------------------------------------------------------------
// Scratch (device globals — allocation-free rule)
// ---------------------------------------------------------------------------
__device__ float g_qkv[8 * 768 * 1024];     // [b][o][hw]   o: 0..255 Q(scaled), 256..511 K, 512..767 V
__device__ float g_attnf[8 * 256 * 1024];   // scrambled attn output [b][c][hw]

// ---------------------------------------------------------------------------
// GEMM + bias (+ optional Q scaling):  C[b][o][n] = sum_c A[o][c]*B[b][c][n] + bias[o]
// A: [M][K_] shared across batch. B: per-batch [K_][1024]. N fixed = 1024.
// Block tile 64(M) x 128(N), BK=16, 256 threads, 4x8 per-thread via f32x2 pairs.
// ---------------------------------------------------------------------------
template<int K_, bool SCALEQ>
__global__ __launch_bounds__(256, 3)
void gemm_bias_kernel(const float* __restrict__ A, const float* __restrict__ B,
                      const float* __restrict__ bias, float* __restrict__ C, int M)
{
    __shared__ float As[16][64];
    __shared__ float Bs[16][128];

    const int b  = blockIdx.z;
    const int n0 = blockIdx.x * 128;
    const int o0 = blockIdx.y * 64;
    const float* Bb = B + (size_t)b * K_ * 1024;
    float*       Cb = C + (size_t)b * M  * 1024;

    const int tid = threadIdx.x;
    const int tx = tid & 15;        // N direction (8 cols each)
    const int ty = tid >> 4;        // M direction (4 rows each)
    const int am = tid >> 2;        // A load row   0..63
    const int ak = (tid & 3) * 4;   // A load k     0,4,8,12
    const int bk = tid >> 4;        // B load k     0..15
    const int bn = (tid & 15) * 8;  // B load col   0..120

    unsigned long long acc[4][4];
#pragma unroll
    for (int i = 0; i < 4; ++i)
#pragma unroll
        for (int j = 0; j < 4; ++j) acc[i][j] = 0ull;

    for (int c0 = 0; c0 < K_; c0 += 16) {
        float4 a4  = *reinterpret_cast<const float4*>(A  + (size_t)(o0 + am) * K_ + c0 + ak);
        float4 b4a = *reinterpret_cast<const float4*>(Bb + (size_t)(c0 + bk) * 1024 + n0 + bn);
        float4 b4b = *reinterpret_cast<const float4*>(Bb + (size_t)(c0 + bk) * 1024 + n0 + bn + 4);
        __syncthreads();
        As[ak + 0][am] = a4.x;
        As[ak + 1][am] = a4.y;
        As[ak + 2][am] = a4.z;
        As[ak + 3][am] = a4.w;
        *reinterpret_cast<float4*>(&Bs[bk][bn])     = b4a;
        *reinterpret_cast<float4*>(&Bs[bk][bn + 4]) = b4b;
        __syncthreads();

#pragma unroll
        for (int kk = 0; kk < 16; ++kk) {
            float4 av = *reinterpret_cast<const float4*>(&As[kk][ty * 4]);
            ulonglong2 bl = *reinterpret_cast<const ulonglong2*>(&Bs[kk][tx * 8]);
            ulonglong2 bh = *reinterpret_cast<const ulonglong2*>(&Bs[kk][tx * 8 + 4]);
            unsigned long long ap;
            ap = pack2(av.x);
            fma2(acc[0][0], ap, bl.x); fma2(acc[0][1], ap, bl.y);
            fma2(acc[0][2], ap, bh.x); fma2(acc[0][3], ap, bh.y);
            ap = pack2(av.y);
            fma2(acc[1][0], ap, bl.x); fma2(acc[1][1], ap, bl.y);
            fma2(acc[1][2], ap, bh.x); fma2(acc[1][3], ap, bh.y);
            ap = pack2(av.z);
            fma2(acc[2][0], ap, bl.x); fma2(acc[2][1], ap, bl.y);
            fma2(acc[2][2], ap, bh.x); fma2(acc[2][3], ap, bh.y);
            ap = pack2(av.w);
            fma2(acc[3][0], ap, bl.x); fma2(acc[3][1], ap, bl.y);
            fma2(acc[3][2], ap, bh.x); fma2(acc[3][3], ap, bh.y);
        }
    }

#pragma unroll
    for (int i = 0; i < 4; ++i) {
        const int o = o0 + ty * 4 + i;
        const float bv = bias[o];
        const float sc = (SCALEQ && o < 256) ? 0.17677669529663687f : 1.0f;
        float r[8];
#pragma unroll
        for (int jp = 0; jp < 4; ++jp) {
            float2 u = unpack2(acc[i][jp]);
            r[2 * jp + 0] = (u.x + bv) * sc;
            r[2 * jp + 1] = (u.y + bv) * sc;
        }
        float* cp = Cb + (size_t)o * 1024 + n0 + tx * 8;
        *reinterpret_cast<float4*>(cp)     = make_float4(r[0], r[1], r[2], r[3]);
        *reinterpret_cast<float4*>(cp + 4) = make_float4(r[4], r[5], r[6], r[7]);
    }
}

// ---------------------------------------------------------------------------
// Fused attention. Grid: (q_tile=32, b=8), 256 threads = (n, qi).
// Softmax is over HEADS (axis=1 in reference) -> purely local per (q,k):
// each thread (n, qi) computes logits l[k], exchanges exp via smem, and its
// own normalized weights never leave registers.
// Output scramble: attnf[b][n*32 + q0/32][qi*32 + d] = attn[n, q0+qi, d].
// ---------------------------------------------------------------------------
__global__ __launch_bounds__(256, 2)
void attn_fused_kernel(const float* __restrict__ qkv, float* __restrict__ attnf)
{
    extern __shared__ float sm[];
    float* Qs  = sm;                 // [256][32]  (d-major, q contiguous)
    float* KVs = sm + 256 * 32;      // K then V: [256][32]
    float* Es  = sm + 2 * 256 * 32;  // exp(logits): [8][32][32] = [n][k][q]

    const int b  = blockIdx.y;
    const int q0 = blockIdx.x * 32;
    const float* QKV = qkv + (size_t)b * 768 * 1024;

    const int tid = threadIdx.x;
    const int n  = tid >> 5;        // head (warp id)
    const int qi = tid & 31;        // q within tile (lane)
    const int lr = tid >> 3;        // loader row base 0..31
    const int lc = (tid & 7) * 4;   // loader col 0..28

    // Load Q tile once (rows 0..255 already scaled by 32^-0.5 in GEMM1)
#pragma unroll
    for (int r = lr; r < 256; r += 32) {
        *reinterpret_cast<float4*>(&Qs[r * 32 + lc]) =
            *reinterpret_cast<const float4*>(QKV + (size_t)r * 1024 + q0 + lc);
    }

    // accP[d] = (sum over even k, sum over odd k) packed pair
    unsigned long long accP[32];
#pragma unroll
    for (int d = 0; d < 32; ++d) accP[d] = 0ull;

    const float* Qb = Qs + n * 1024;   // head-n Q rows
    const float* Kb = KVs + n * 1024;  // head-n K rows (valid while K resident)

    for (int kt = 0; kt < 32; ++kt) {
        const int k0 = kt * 32;

        __syncthreads();  // prior V/Es consumers done
        // --- load K tile (rows 256..511) ---
#pragma unroll
        for (int r = lr; r < 256; r += 32) {
            *reinterpret_cast<float4*>(&KVs[r * 32 + lc]) =
                *reinterpret_cast<const float4*>(QKV + (size_t)(256 + r) * 1024 + k0 + lc);
        }
        __syncthreads();

        // --- Phase A: logits l2 pairs over k ---
        unsigned long long l2[16];
#pragma unroll
        for (int p = 0; p < 16; ++p) l2[p] = 0ull;
#pragma unroll 4
        for (int d = 0; d < 32; ++d) {
            unsigned long long qq = pack2(Qb[d * 32 + qi]);
#pragma unroll
            for (int p = 0; p < 8; ++p) {
                ulonglong2 kk = *reinterpret_cast<const ulonglong2*>(&Kb[d * 32 + p * 4]);
                fma2(l2[2 * p + 0], qq, kk.x);
                fma2(l2[2 * p + 1], qq, kk.y);
            }
        }

        // --- exp, publish to Es[n][k][qi] ---
        float* eb = Es + n * 1024 + qi;
#pragma unroll
        for (int p = 0; p < 16; ++p) {
            float2 lv = unpack2(l2[p]);
            eb[(2 * p + 0) * 32] = __expf(lv.x);
            eb[(2 * p + 1) * 32] = __expf(lv.y);
        }
        __syncthreads();  // K reads done; Es visible

        // --- load V tile (rows 512..767) into same buffer ---
#pragma unroll
        for (int r = lr; r < 256; r += 32) {
            *reinterpret_cast<float4*>(&KVs[r * 32 + lc]) =
                *reinterpret_cast<const float4*>(QKV + (size_t)(512 + r) * 1024 + k0 + lc);
        }
        __syncthreads();  // V visible

        // --- Phase B: softmax over heads + PV accumulation ---
        const float* Vh = KVs + n * 1024;
        for (int k4 = 0; k4 < 32; k4 += 4) {
            float s0 = 0.f, s1 = 0.f, s2 = 0.f, s3 = 0.f;
#pragma unroll
            for (int n2 = 0; n2 < 8; ++n2) {
                const float* ep = Es + n2 * 1024 + k4 * 32 + qi;
                s0 += ep[0];  s1 += ep[32];  s2 += ep[64];  s3 += ep[96];
            }
            const float* eo = Es + n * 1024 + k4 * 32 + qi;
            const float w0 = __fdividef(eo[0],  s0);
            const float w1 = __fdividef(eo[32], s1);
            const float w2 = __fdividef(eo[64], s2);
            const float w3 = __fdividef(eo[96], s3);
            const unsigned long long w01 = pack2(w0, w1);
            const unsigned long long w23 = pack2(w2, w3);
            const float* Vk = Vh + k4;
#pragma unroll
            for (int d = 0; d < 32; ++d) {
                ulonglong2 vv = *reinterpret_cast<const ulonglong2*>(Vk + d * 32);
                fma2(accP[d], w01, vv.x);
                fma2(accP[d], w23, vv.y);
            }
        }
    }

    // --- write scrambled output: c = n*32 + q0/32, hw = qi*32 + d ---
    float* orow = attnf + ((size_t)b * 256 + n * 32 + (q0 >> 5)) * 1024 + qi * 32;
#pragma unroll
    for (int d4 = 0; d4 < 32; d4 += 4) {
        float2 p0 = unpack2(accP[d4 + 0]);
        float2 p1 = unpack2(accP[d4 + 1]);
        float2 p2 = unpack2(accP[d4 + 2]);
        float2 p3 = unpack2(accP[d4 + 3]);
        *reinterpret_cast<float4*>(orow + d4) =
            make_float4(p0.x + p0.y, p1.x + p1.y, p2.x + p2.y, p3.x + p3.y);
    }
}

// ---------------------------------------------------------------------------
// Launch: QKV GEMM -> fused attention -> output GEMM (same stream, capturable)
// ---------------------------------------------------------------------------
extern "C" void kernel_launch(void* const* d_in, const int* in_sizes, int n_in,
                              void* d_out, int out_size)
{
    (void)in_sizes; (void)n_in; (void)out_size;
    const float* x      = (const float*)d_in[0];   // [8][512][1024]
    const float* w_qkv  = (const float*)d_in[1];   // [768][512]
    const float* b_qkv  = (const float*)d_in[2];   // [768]
    const float* w_attn = (const float*)d_in[3];   // [512][256]
    const float* b_attn = (const float*)d_in[4];   // [512]
    float* out = (float*)d_out;                    // [8][512][1024]

    float *qkv = nullptr, *attnf = nullptr;
    cudaGetSymbolAddress((void**)&qkv, g_qkv);
    cudaGetSymbolAddress((void**)&attnf, g_attnf);

    cudaFuncSetAttribute(attn_fused_kernel,
                         cudaFuncAttributeMaxDynamicSharedMemorySize, 98304);

    // 1) QKV projection + bias, Q rows scaled by 32^-0.5
    gemm_bias_kernel<512, true><<<dim3(8, 12, 8), 256>>>(w_qkv, x, b_qkv, qkv, 768);

    // 2) fused logits / head-softmax / PV with output scramble
    attn_fused_kernel<<<dim3(32, 8), 256, 98304>>>(qkv, attnf);

    // 3) output projection + bias
    gemm_bias_kernel<256, false><<<dim3(8, 8, 8), 256>>>(w_attn, attnf, b_attn, out, 512);
}

// round 5
// speedup vs baseline: 1.3561x; 1.3561x over previous
#include <cuda_runtime.h>

#define DEV_INLINE __device__ __forceinline__
typedef unsigned long long u64;

// ---------------------------------------------------------------------------
// Packed f32x2 helpers (FFMA2 path)
// ---------------------------------------------------------------------------
DEV_INLINE u64 pack2(float x) {
    u64 r;
    asm("mov.b64 %0, {%1, %1};" : "=l"(r) : "r"(__float_as_uint(x)));
    return r;
}
DEV_INLINE u64 pack2(float x, float y) {
    u64 r;
    asm("mov.b64 %0, {%1, %2};" : "=l"(r) : "r"(__float_as_uint(x)), "r"(__float_as_uint(y)));
    return r;
}
DEV_INLINE void fma2(u64& d, u64 a, u64 b) {
    asm("fma.rn.f32x2 %0, %1, %2, %0;" : "+l"(d) : "l"(a), "l"(b));
}
DEV_INLINE float2 unpack2(u64 v) {
    unsigned int lo, hi;
    asm("mov.b64 {%0, %1}, %2;" : "=r"(lo), "=r"(hi) : "l"(v));
    return make_float2(__uint_as_float(lo), __uint_as_float(hi));
}

// cp.async helpers
DEV_INLINE void cp16(float* dst, const float* src) {
    unsigned d = (unsigned)__cvta_generic_to_shared(dst);
    asm volatile("cp.async.cg.shared.global [%0], [%1], 16;" :: "r"(d), "l"(src) : "memory");
}
DEV_INLINE void cp_commit() { asm volatile("cp.async.commit_group;" ::: "memory"); }
DEV_INLINE void cp_wait0()  { asm volatile("cp.async.wait_group 0;"  ::: "memory"); }

// ---------------------------------------------------------------------------
// Scratch (device globals — allocation-free rule)
// ---------------------------------------------------------------------------
__device__ float g_qkv[8 * 768 * 1024];     // [b][o][hw]  o: 0..255 Q(scaled), 256..511 K, 512..767 V
__device__ float g_attnf[8 * 256 * 1024];   // scrambled attn output [b][c][hw]

// ---------------------------------------------------------------------------
// GEMM + bias (+ optional Q scaling):  C[b][o][n] = sum_c A[o][c]*B[b][c][n] + bias[o]
// 128x128 block tile, BK=16, 256 threads, 8x8 per-thread, double-buffered smem.
// ---------------------------------------------------------------------------
template<int K_, bool SCALEQ>
__global__ __launch_bounds__(256, 2)
void gemm_kernel(const float* __restrict__ A, const float* __restrict__ B,
                 const float* __restrict__ bias, float* __restrict__ C, int M)
{
    constexpr int NIT = K_ / 16;
    __shared__ float As[2][16][132];   // k-major, padded (132)
    __shared__ float Bs[2][16][128];

    const int b  = blockIdx.z;
    const int n0 = blockIdx.x * 128;
    const int o0 = blockIdx.y * 128;
    const float* Bb = B + (size_t)b * K_ * 1024;
    float*       Cb = C + (size_t)b * M  * 1024;

    const int tid  = threadIdx.x;
    const int tx   = tid & 15;          // cols: tx*4..+3 and 64+tx*4..+3
    const int ty   = tid >> 4;          // rows: ty*8..+7
    const int arow = tid >> 1;          // A loader row 0..127
    const int acol = (tid & 1) * 8;     // A loader k base {0,8}
    const int brow = tid >> 5;          // B loader k rows {brow, brow+8}
    const int bcol = (tid & 31) * 4;    // B loader col 0..124

    u64 acc[8][4];
#pragma unroll
    for (int i = 0; i < 8; ++i)
#pragma unroll
        for (int j = 0; j < 4; ++j) acc[i][j] = 0ull;

    const float* Ag = A  + (size_t)(o0 + arow) * K_ + acol;
    const float* Bg = Bb + (size_t)brow * 1024 + n0 + bcol;

    // prologue: tile 0
    float4 a0 = *reinterpret_cast<const float4*>(Ag);
    float4 a1 = *reinterpret_cast<const float4*>(Ag + 4);
    float4 b0 = *reinterpret_cast<const float4*>(Bg);
    float4 b1 = *reinterpret_cast<const float4*>(Bg + 8 * 1024);
    {
        As[0][acol + 0][arow] = a0.x; As[0][acol + 1][arow] = a0.y;
        As[0][acol + 2][arow] = a0.z; As[0][acol + 3][arow] = a0.w;
        As[0][acol + 4][arow] = a1.x; As[0][acol + 5][arow] = a1.y;
        As[0][acol + 6][arow] = a1.z; As[0][acol + 7][arow] = a1.w;
        *reinterpret_cast<float4*>(&Bs[0][brow][bcol])     = b0;
        *reinterpret_cast<float4*>(&Bs[0][brow + 8][bcol]) = b1;
    }
    __syncthreads();

    for (int it = 0; it < NIT; ++it) {
        const int cur = it & 1;
        if (it + 1 < NIT) {   // prefetch next tile into registers
            const float* Ag2 = Ag + (it + 1) * 16;
            const float* Bg2 = Bg + (size_t)(it + 1) * 16 * 1024;
            a0 = *reinterpret_cast<const float4*>(Ag2);
            a1 = *reinterpret_cast<const float4*>(Ag2 + 4);
            b0 = *reinterpret_cast<const float4*>(Bg2);
            b1 = *reinterpret_cast<const float4*>(Bg2 + 8 * 1024);
        }

#pragma unroll
        for (int kk = 0; kk < 16; ++kk) {
            float4 aA = *reinterpret_cast<const float4*>(&As[cur][kk][ty * 8]);
            float4 aB = *reinterpret_cast<const float4*>(&As[cur][kk][ty * 8 + 4]);
            float4 bA = *reinterpret_cast<const float4*>(&Bs[cur][kk][tx * 4]);
            float4 bB = *reinterpret_cast<const float4*>(&Bs[cur][kk][64 + tx * 4]);
            u64 bp0 = pack2(bA.x, bA.y), bp1 = pack2(bA.z, bA.w);
            u64 bp2 = pack2(bB.x, bB.y), bp3 = pack2(bB.z, bB.w);
            u64 ap;
            ap = pack2(aA.x); fma2(acc[0][0], ap, bp0); fma2(acc[0][1], ap, bp1); fma2(acc[0][2], ap, bp2); fma2(acc[0][3], ap, bp3);
            ap = pack2(aA.y); fma2(acc[1][0], ap, bp0); fma2(acc[1][1], ap, bp1); fma2(acc[1][2], ap, bp2); fma2(acc[1][3], ap, bp3);
            ap = pack2(aA.z); fma2(acc[2][0], ap, bp0); fma2(acc[2][1], ap, bp1); fma2(acc[2][2], ap, bp2); fma2(acc[2][3], ap, bp3);
            ap = pack2(aA.w); fma2(acc[3][0], ap, bp0); fma2(acc[3][1], ap, bp1); fma2(acc[3][2], ap, bp2); fma2(acc[3][3], ap, bp3);
            ap = pack2(aB.x); fma2(acc[4][0], ap, bp0); fma2(acc[4][1], ap, bp1); fma2(acc[4][2], ap, bp2); fma2(acc[4][3], ap, bp3);
            ap = pack2(aB.y); fma2(acc[5][0], ap, bp0); fma2(acc[5][1], ap, bp1); fma2(acc[5][2], ap, bp2); fma2(acc[5][3], ap, bp3);
            ap = pack2(aB.z); fma2(acc[6][0], ap, bp0); fma2(acc[6][1], ap, bp1); fma2(acc[6][2], ap, bp2); fma2(acc[6][3], ap, bp3);
            ap = pack2(aB.w); fma2(acc[7][0], ap, bp0); fma2(acc[7][1], ap, bp1); fma2(acc[7][2], ap, bp2); fma2(acc[7][3], ap, bp3);
        }

        if (it + 1 < NIT) {   // store prefetched tile into the other buffer
            const int nb = cur ^ 1;
            As[nb][acol + 0][arow] = a0.x; As[nb][acol + 1][arow] = a0.y;
            As[nb][acol + 2][arow] = a0.z; As[nb][acol + 3][arow] = a0.w;
            As[nb][acol + 4][arow] = a1.x; As[nb][acol + 5][arow] = a1.y;
            As[nb][acol + 6][arow] = a1.z; As[nb][acol + 7][arow] = a1.w;
            *reinterpret_cast<float4*>(&Bs[nb][brow][bcol])     = b0;
            *reinterpret_cast<float4*>(&Bs[nb][brow + 8][bcol]) = b1;
            __syncthreads();
        }
    }

    // epilogue: bias (+ Q scale), write C
#pragma unroll
    for (int i = 0; i < 8; ++i) {
        const int o = o0 + ty * 8 + i;
        const float bv = bias[o];
        const float sc = (SCALEQ && o < 256) ? 0.17677669529663687f : 1.0f;
        float2 u0 = unpack2(acc[i][0]), u1 = unpack2(acc[i][1]);
        float2 u2 = unpack2(acc[i][2]), u3 = unpack2(acc[i][3]);
        float* cp = Cb + (size_t)o * 1024 + n0;
        *reinterpret_cast<float4*>(cp + tx * 4) =
            make_float4((u0.x + bv) * sc, (u0.y + bv) * sc, (u1.x + bv) * sc, (u1.y + bv) * sc);
        *reinterpret_cast<float4*>(cp + 64 + tx * 4) =
            make_float4((u2.x + bv) * sc, (u2.y + bv) * sc, (u3.x + bv) * sc, (u3.y + bv) * sc);
    }
}

// ---------------------------------------------------------------------------
// Fused attention (softmax over HEADS — local per (q,k)).
// Grid: (q_tile=32, b=8). 512 threads = 16 warps = (head n, k-half h).
// cp.async double-buffered K/V (full load/compute overlap), cooperative
// reciprocal head-sum pass, k-split accumulators merged through smem.
// smem: Qs 32K | K x2 64K | V x2 64K | Es 32K | Rs 4K = 196 KB (1 CTA/SM)
// ---------------------------------------------------------------------------
__global__ __launch_bounds__(512, 1)
void attn_kernel(const float* __restrict__ qkv, float* __restrict__ attnf)
{
    extern __shared__ float sm[];
    float* Qs = sm;              // [256][32]
    float* Kbuf = sm + 8192;     // 2 x [256][32]
    float* Vbuf = sm + 24576;    // 2 x [256][32]
    float* Es = sm + 40960;      // [8][32][32] = [n][k][qi]
    float* Rs = sm + 49152;      // [32][32]    = [k][qi] reciprocal head-sums

    const int b  = blockIdx.y;
    const int q0 = blockIdx.x * 32;
    const float* QKV = qkv + (size_t)b * 768 * 1024;

    const int tid  = threadIdx.x;
    const int warp = tid >> 5;
    const int n    = warp >> 1;     // head
    const int h    = warp & 1;      // k-half (16 keys)
    const int qi   = tid & 31;

    // ---- load Q tile (plain loads, once) ----
#pragma unroll
    for (int c = 0; c < 4; ++c) {
        int i = tid + c * 512;
        int r = i >> 3, cg = (i & 7) * 4;
        *reinterpret_cast<float4*>(&Qs[r * 32 + cg]) =
            *reinterpret_cast<const float4*>(QKV + (size_t)r * 1024 + q0 + cg);
    }

    // ---- prologue: async K/V loads for kt=0 ----
    {
        const int k0 = 0;
#pragma unroll
        for (int c = 0; c < 4; ++c) {
            int i = tid + c * 512;
            int r = i >> 3, cg = (i & 7) * 4;
            cp16(&Kbuf[r * 32 + cg], QKV + (size_t)(256 + r) * 1024 + k0 + cg);
            cp16(&Vbuf[r * 32 + cg], QKV + (size_t)(512 + r) * 1024 + k0 + cg);
        }
        cp_commit();
    }

    u64 acc[32];
#pragma unroll
    for (int d = 0; d < 32; ++d) acc[d] = 0ull;

    for (int kt = 0; kt < 32; ++kt) {
        const int cur = kt & 1;
        cp_wait0();
        __syncthreads();   // buffers for kt valid; everyone past phase B(kt-1)

        if (kt < 31) {     // prefetch kt+1 into the other buffer (overlaps compute)
            const int k0 = (kt + 1) * 32;
            float* Kn = Kbuf + (cur ^ 1) * 8192;
            float* Vn = Vbuf + (cur ^ 1) * 8192;
#pragma unroll
            for (int c = 0; c < 4; ++c) {
                int i = tid + c * 512;
                int r = i >> 3, cg = (i & 7) * 4;
                cp16(&Kn[r * 32 + cg], QKV + (size_t)(256 + r) * 1024 + k0 + cg);
                cp16(&Vn[r * 32 + cg], QKV + (size_t)(512 + r) * 1024 + k0 + cg);
            }
            cp_commit();
        }

        const float* K = Kbuf + cur * 8192;
        const float* V = Vbuf + cur * 8192;

        // ---- Phase A: logits for my 16 keys, exp -> Es[n][k][qi] ----
        {
            const float* Kp = K + n * 1024 + h * 16;
            const float* Qp = Qs + n * 1024 + qi;
            u64 l2[8];
#pragma unroll
            for (int p = 0; p < 8; ++p) l2[p] = 0ull;
#pragma unroll
            for (int d = 0; d < 32; ++d) {
                u64 qq = pack2(Qp[d * 32]);
                ulonglong2 kA = *reinterpret_cast<const ulonglong2*>(Kp + d * 32);
                ulonglong2 kB = *reinterpret_cast<const ulonglong2*>(Kp + d * 32 + 4);
                ulonglong2 kC = *reinterpret_cast<const ulonglong2*>(Kp + d * 32 + 8);
                ulonglong2 kD = *reinterpret_cast<const ulonglong2*>(Kp + d * 32 + 12);
                fma2(l2[0], qq, kA.x); fma2(l2[1], qq, kA.y);
                fma2(l2[2], qq, kB.x); fma2(l2[3], qq, kB.y);
                fma2(l2[4], qq, kC.x); fma2(l2[5], qq, kC.y);
                fma2(l2[6], qq, kD.x); fma2(l2[7], qq, kD.y);
            }
            float* eb = Es + n * 1024 + (h * 16) * 32 + qi;
#pragma unroll
            for (int p = 0; p < 8; ++p) {
                float2 lv = unpack2(l2[p]);
                eb[(2 * p + 0) * 32] = __expf(lv.x);
                eb[(2 * p + 1) * 32] = __expf(lv.y);
            }
        }
        __syncthreads();

        // ---- Rs pass: Rs[k][qi] = 1 / sum_n Es[n][k][qi] ----
#pragma unroll
        for (int pp = 0; pp < 2; ++pp) {
            int p = tid + pp * 512;
            float s = Es[p] + Es[1024 + p] + Es[2048 + p] + Es[3072 + p]
                    + Es[4096 + p] + Es[5120 + p] + Es[6144 + p] + Es[7168 + p];
            Rs[p] = __fdividef(1.0f, s);
        }
        __syncthreads();

        // ---- Phase B: weights + PV accumulation over my 16 keys ----
        {
            const float* Vp = V + n * 1024;
            const float* ep = Es + n * 1024 + qi;
            const float* rp = Rs + qi;
#pragma unroll
            for (int g = 0; g < 4; ++g) {
                const int k = h * 16 + g * 4;
                const float w0 = ep[(k + 0) * 32] * rp[(k + 0) * 32];
                const float w1 = ep[(k + 1) * 32] * rp[(k + 1) * 32];
                const float w2 = ep[(k + 2) * 32] * rp[(k + 2) * 32];
                const float w3 = ep[(k + 3) * 32] * rp[(k + 3) * 32];
                const u64 w01 = pack2(w0, w1);
                const u64 w23 = pack2(w2, w3);
                const float* Vk = Vp + k;
#pragma unroll
                for (int d = 0; d < 32; ++d) {
                    ulonglong2 vv = *reinterpret_cast<const ulonglong2*>(Vk + d * 32);
                    fma2(acc[d], w01, vv.x);
                    fma2(acc[d], w23, vv.y);
                }
            }
        }
        // next iteration's top wait+sync orders buffer reuse
    }

    // ---- merge k-halves, write scrambled output ----
    __syncthreads();   // all phase B done; Es/Rs now reusable as staging
    float res[32];
#pragma unroll
    for (int d = 0; d < 32; ++d) {
        float2 u = unpack2(acc[d]);
        res[d] = u.x + u.y;
    }
    float* stage = Es;                       // pitch 36 floats (uses Es+Rs space)
    float* srow = stage + (n * 32 + qi) * 36;
    if (h == 0) {
#pragma unroll
        for (int d = 0; d < 32; d += 4)
            *reinterpret_cast<float4*>(&srow[d]) =
                make_float4(res[d], res[d + 1], res[d + 2], res[d + 3]);
    }
    __syncthreads();
    if (h == 1) {
        float* orow = attnf + ((size_t)b * 256 + n * 32 + (q0 >> 5)) * 1024 + qi * 32;
#pragma unroll
        for (int d = 0; d < 32; d += 4) {
            float4 o = *reinterpret_cast<const float4*>(&srow[d]);
            *reinterpret_cast<float4*>(orow + d) =
                make_float4(res[d] + o.x, res[d + 1] + o.y, res[d + 2] + o.z, res[d + 3] + o.w);
        }
    }
}

// ---------------------------------------------------------------------------
// Launch
// ---------------------------------------------------------------------------
extern "C" void kernel_launch(void* const* d_in, const int* in_sizes, int n_in,
                              void* d_out, int out_size)
{
    (void)in_sizes; (void)n_in; (void)out_size;
    const float* x      = (const float*)d_in[0];   // [8][512][1024]
    const float* w_qkv  = (const float*)d_in[1];   // [768][512]
    const float* b_qkv  = (const float*)d_in[2];   // [768]
    const float* w_attn = (const float*)d_in[3];   // [512][256]
    const float* b_attn = (const float*)d_in[4];   // [512]
    float* out = (float*)d_out;                    // [8][512][1024]

    float *qkv = nullptr, *attnf = nullptr;
    cudaGetSymbolAddress((void**)&qkv, g_qkv);
    cudaGetSymbolAddress((void**)&attnf, g_attnf);

    cudaFuncSetAttribute(attn_kernel,
                         cudaFuncAttributeMaxDynamicSharedMemorySize, 200704);

    // 1) QKV projection + bias, Q rows scaled by 32^-0.5
    gemm_kernel<512, true><<<dim3(8, 6, 8), 256>>>(w_qkv, x, b_qkv, qkv, 768);

    // 2) fused logits / head-softmax / PV with output scramble
    attn_kernel<<<dim3(32, 8), 512, 200704>>>(qkv, attnf);

    // 3) output projection + bias
    gemm_kernel<256, false><<<dim3(8, 4, 8), 256>>>(w_attn, attnf, b_attn, out, 512);
}